// round 4
// baseline (speedup 1.0000x reference)
#include <cuda_runtime.h>
#include <cuda_bf16.h>
#include <stdint.h>

#define B_DIM   8192
#define F0_DIM  2048
#define F1_DIM  2304
#define F2_DIM  2560
#define O_DIM   1024
#define NNZ_DIM 262144
#define NB_DIM  1024
#define KA_DIM  5120   /* A int8 storage: [q_hi | q_lo], bytes per row */
#define KB_DIM  7680   /* B int8 storage: [w_hi | w_lo | w_hi], bytes per row */

// ---------------- scratch (device globals; no allocation allowed) -------------
__device__ float g_W[O_DIM * F2_DIM];
__device__ float g_bias[O_DIM];
__device__ float g_sA[B_DIM];
__device__ float g_sB[O_DIM];
__device__ signed char g_A[(size_t)B_DIM * KA_DIM];    // 42 MB
__device__ signed char g_Bc[(size_t)O_DIM * KB_DIM];   // 7.9 MB

// ---------------- helpers -----------------------------------------------------
__device__ __forceinline__ uint32_t smem_u32(const void* p) {
    uint32_t a;
    asm("{ .reg .u64 t; cvta.to.shared.u64 t, %1; cvt.u32.u64 %0, t; }"
        : "=r"(a) : "l"(p));
    return a;
}

#define SW128(off) ((uint32_t)(off) ^ ((((uint32_t)(off)) >> 3) & 0x70u))

__device__ __forceinline__ void cp_async16(uint32_t saddr, const void* gptr) {
    asm volatile("cp.async.cg.shared.global [%0], [%1], 16;\n"
                 :: "r"(saddr), "l"(gptr));
}

__device__ __forceinline__ void ldsm_x4(uint32_t* r, uint32_t addr) {
    asm volatile("ldmatrix.sync.aligned.m8n8.x4.shared.b16 {%0,%1,%2,%3}, [%4];"
                 : "=r"(r[0]), "=r"(r[1]), "=r"(r[2]), "=r"(r[3]) : "r"(addr));
}

__device__ __forceinline__ void mma_s8(int* d, const uint32_t* a, const uint32_t* b) {
    asm volatile(
        "mma.sync.aligned.m16n8k32.row.col.s32.s8.s8.s32 "
        "{%0,%1,%2,%3}, {%4,%5,%6,%7}, {%8,%9}, {%0,%1,%2,%3};\n"
        : "+r"(d[0]), "+r"(d[1]), "+r"(d[2]), "+r"(d[3])
        : "r"(a[0]), "r"(a[1]), "r"(a[2]), "r"(a[3]), "r"(b[0]), "r"(b[1]));
}

__device__ __forceinline__ int clamp127(int v) {
    return v > 127 ? 127 : (v < -127 ? -127 : v);
}

// quantize float -> (hi, lo) int8 pair given inverse scale; q = hi + lo/256
__device__ __forceinline__ void quant2(float v, float inv, int& hi, int& lo) {
    float q = v * inv;
    hi = __float2int_rn(q);
    lo = clamp127(__float2int_rn((q - (float)hi) * 256.0f));
}

// ---------------- prologue kernels -------------------------------------------
__global__ void zero_kernel() {
    int i = blockIdx.x * blockDim.x + threadIdx.x;
    if (i < O_DIM * F2_DIM) g_W[i] = 0.0f;
    if (i < O_DIM) g_bias[i] = 0.0f;
}

__global__ void scatter_kernel(const float* __restrict__ w_vals,
                               const int*   __restrict__ w_rows,
                               const int*   __restrict__ w_cols,
                               const float* __restrict__ b_vals,
                               const int*   __restrict__ b_idx) {
    int i = blockIdx.x * blockDim.x + threadIdx.x;
    if (i < NNZ_DIM)
        atomicAdd(&g_W[w_rows[i] * F2_DIM + w_cols[i]], w_vals[i]);
    if (i < NB_DIM)
        atomicAdd(&g_bias[b_idx[i]], b_vals[i]);
}

// per output row: rowmax -> scale -> int8 hi/lo, layout [hi | lo | hi]
__global__ void __launch_bounds__(256)
convw_kernel() {
    __shared__ float wmax[8];
    __shared__ float s_inv;
    const int tid = threadIdx.x;
    const int o = blockIdx.x;
    const float* row = g_W + (size_t)o * F2_DIM;

    float m = 0.0f;
#pragma unroll
    for (int t = 0; t < 10; t++)
        m = fmaxf(m, fabsf(row[tid + t * 256]));
#pragma unroll
    for (int s = 16; s > 0; s >>= 1)
        m = fmaxf(m, __shfl_xor_sync(0xFFFFFFFFu, m, s));
    if ((tid & 31) == 0) wmax[tid >> 5] = m;
    __syncthreads();
    if (tid == 0) {
        float mm = 0.0f;
#pragma unroll
        for (int w = 0; w < 8; w++) mm = fmaxf(mm, wmax[w]);
        mm = fmaxf(mm, 1e-30f);
        g_sB[o] = mm / 127.0f;
        s_inv = 127.0f / mm;
    }
    __syncthreads();
    const float inv = s_inv;

    signed char* base = g_Bc + (size_t)o * KB_DIM;
#pragma unroll
    for (int t = 0; t < 3; t++) {
        int i = tid + t * 256;
        if (i < F2_DIM / 4) {
            float4 v = *(const float4*)(row + i * 4);
            int h0, l0, h1, l1, h2, l2, h3, l3;
            quant2(v.x, inv, h0, l0);
            quant2(v.y, inv, h1, l1);
            quant2(v.z, inv, h2, l2);
            quant2(v.w, inv, h3, l3);
            char4 hc = make_char4((char)h0, (char)h1, (char)h2, (char)h3);
            char4 lc = make_char4((char)l0, (char)l1, (char)l2, (char)l3);
            *(char4*)(base + i * 4)              = hc;
            *(char4*)(base + F2_DIM + i * 4)     = lc;
            *(char4*)(base + 2 * F2_DIM + i * 4) = hc;
        }
    }
}

// one block per batch row; gathers in smem, then rowmax + int8 hi/lo quantize
__global__ void __launch_bounds__(256)
build_a_kernel(const float* __restrict__ x,
               const float* __restrict__ e1w,
               const float* __restrict__ e2w,
               const int*   __restrict__ e1p,
               const int*   __restrict__ e2p) {
    __shared__ float sh[F2_DIM];
    __shared__ float wmax[8];
    __shared__ float s_inv;
    const int tid = threadIdx.x;
    const int b = blockIdx.x;

    const float4* xr = (const float4*)(x + (size_t)b * F0_DIM);
#pragma unroll
    for (int t = 0; t < F0_DIM / 4 / 256; t++)          // 2 iters
        ((float4*)sh)[tid + t * 256] = xr[tid + t * 256];
    __syncthreads();

    {   // E1 == 256 == blockDim
        int c = tid;
        float t = sh[__ldg(&e1p[c])] * __ldg(&e1w[c]);
        sh[F0_DIM + c] = fmaxf(t, 0.0f);
    }
    __syncthreads();
    {   // E2 == 256
        int c = tid;
        float t = sh[__ldg(&e2p[c])] * __ldg(&e2w[c]);
        sh[F1_DIM + c] = fmaxf(t, 0.0f);
    }
    __syncthreads();

    float m = 0.0f;
#pragma unroll
    for (int t = 0; t < 10; t++)
        m = fmaxf(m, fabsf(sh[tid + t * 256]));
#pragma unroll
    for (int s = 16; s > 0; s >>= 1)
        m = fmaxf(m, __shfl_xor_sync(0xFFFFFFFFu, m, s));
    if ((tid & 31) == 0) wmax[tid >> 5] = m;
    __syncthreads();
    if (tid == 0) {
        float mm = 0.0f;
#pragma unroll
        for (int w = 0; w < 8; w++) mm = fmaxf(mm, wmax[w]);
        mm = fmaxf(mm, 1e-30f);
        g_sA[b] = mm / 127.0f;
        s_inv = 127.0f / mm;
    }
    __syncthreads();
    const float inv = s_inv;

    signed char* base = g_A + (size_t)b * KA_DIM;
#pragma unroll
    for (int t = 0; t < 3; t++) {
        int i = tid + t * 256;
        if (i < F2_DIM / 4) {
            float4 v = *(const float4*)(sh + i * 4);
            int h0, l0, h1, l1, h2, l2, h3, l3;
            quant2(v.x, inv, h0, l0);
            quant2(v.y, inv, h1, l1);
            quant2(v.z, inv, h2, l2);
            quant2(v.w, inv, h3, l3);
            *(char4*)(base + i * 4) = make_char4((char)h0, (char)h1, (char)h2, (char)h3);
            *(char4*)(base + F2_DIM + i * 4) = make_char4((char)l0, (char)l1, (char)l2, (char)l3);
        }
    }
}

// ---------------- int8 HMMA GEMM: out = sA*sB*(acc/256) + bias ----------------
#define BM 128
#define BN 256
#define BK 128                              /* int8 k-elems == bytes per row */
#define STAGES 4
#define A_STAGE (BM * BK)                   /* 16384 B */
#define B_STAGE (BN * BK)                   /* 32768 B */
#define STAGE_BYTES (A_STAGE + B_STAGE)     /* 49152 B */
#define KT (KB_DIM / BK)                    /* 60 */
#define KT_PHASE0 (F2_DIM / BK)             /* 20: hi*hi phase, then acc<<=8 */
#define DYN_SMEM (STAGES * STAGE_BYTES)     /* 196608 B */

__global__ void __launch_bounds__(256, 1)
gemm_kernel(float* __restrict__ out) {
    extern __shared__ char dynsm[];
    const int tid  = threadIdx.x;
    const int wid  = tid >> 5;
    const int lane = tid & 31;
    const int wm   = wid >> 2;       // 0..1, 64 rows each
    const int wn   = wid & 3;        // 0..3, 64 cols each
    const int m0 = blockIdx.x * BM;
    const int n0 = blockIdx.y * BN;
    const uint32_t smbase = smem_u32(dynsm);

    int acc[4][8][4];
#pragma unroll
    for (int mt = 0; mt < 4; mt++)
#pragma unroll
        for (int nt = 0; nt < 8; nt++)
#pragma unroll
            for (int r = 0; r < 4; r++) acc[mt][nt][r] = 0;

    // ldmatrix lane address components (logical, pre-swizzle, byte units)
    const uint32_t a_row = (uint32_t)(wm * 64 + (lane & 15));
    const uint32_t a_col = (uint32_t)((lane >> 4) * 16);
    const uint32_t b_row = (uint32_t)(wn * 64 + (lane & 7) + ((lane >> 4) << 3));
    const uint32_t b_col = (uint32_t)(((lane >> 3) & 1) * 16);

    auto load_tile = [&](int s, int kt) {
        int k0  = kt * BK;
        int ak0 = (k0 >= F2_DIM) ? (k0 - F2_DIM) : k0;   // A phase fold
        uint32_t As = smbase + s * STAGE_BYTES;
        uint32_t Bs = As + A_STAGE;
        const signed char* gA = g_A  + ak0;
        const signed char* gB = g_Bc + k0;
#pragma unroll
        for (int t = 0; t < 4; t++) {                    // A: 1024 16B ops
            int o = tid + t * 256;
            int r = o >> 3;
            int c = (o & 7) * 16;
            cp_async16(As + SW128(r * 128 + c),
                       gA + (size_t)(m0 + r) * KA_DIM + c);
        }
#pragma unroll
        for (int t = 0; t < 8; t++) {                    // B: 2048 16B ops
            int o = tid + t * 256;
            int r = o >> 3;
            int c = (o & 7) * 16;
            cp_async16(Bs + SW128(r * 128 + c),
                       gB + (size_t)(n0 + r) * KB_DIM + c);
        }
    };

#pragma unroll
    for (int s = 0; s < STAGES - 1; s++) {
        load_tile(s, s);
        asm volatile("cp.async.commit_group;\n");
    }

    for (int kt = 0; kt < KT; kt++) {
        asm volatile("cp.async.wait_group %0;\n" :: "n"(STAGES - 2));
        __syncthreads();

        int kn = kt + STAGES - 1;
        if (kn < KT) load_tile(kn & (STAGES - 1), kn);
        asm volatile("cp.async.commit_group;\n");

        if (kt == KT_PHASE0) {   // hi*hi phase done: weight it by 256
#pragma unroll
            for (int mt = 0; mt < 4; mt++)
#pragma unroll
                for (int nt = 0; nt < 8; nt++)
#pragma unroll
                    for (int r = 0; r < 4; r++) acc[mt][nt][r] <<= 8;
        }

        const uint32_t As = smbase + (kt & (STAGES - 1)) * STAGE_BYTES;
        const uint32_t Bs = As + A_STAGE;
#pragma unroll
        for (int ks = 0; ks < 4; ks++) {                 // BK=128 -> 4 k32 steps
            uint32_t a[4][4], b[4][4];
#pragma unroll
            for (int mt = 0; mt < 4; mt++)
                ldsm_x4(a[mt], As + SW128((a_row + mt * 16) * 128 + ks * 32 + a_col));
#pragma unroll
            for (int n2 = 0; n2 < 4; n2++)
                ldsm_x4(b[n2], Bs + SW128((b_row + n2 * 16) * 128 + ks * 32 + b_col));
#pragma unroll
            for (int mt = 0; mt < 4; mt++)
#pragma unroll
                for (int nt = 0; nt < 8; nt++)
                    mma_s8(acc[mt][nt], a[mt], &b[nt >> 1][(nt & 1) * 2]);
        }
    }

    // epilogue: scale + bias, float2 stores
    const int r0 = m0 + wm * 64 + (lane >> 2);
    const int c0 = n0 + wn * 64 + (lane & 3) * 2;
#pragma unroll
    for (int mt = 0; mt < 4; mt++) {
        int row = r0 + mt * 16;
        float sa0 = g_sA[row] * (1.0f / 256.0f);
        float sa1 = g_sA[row + 8] * (1.0f / 256.0f);
#pragma unroll
        for (int nt = 0; nt < 8; nt++) {
            int col = c0 + nt * 8;
            float2 bv = *(const float2*)(g_bias + col);
            float sb0 = g_sB[col], sb1 = g_sB[col + 1];
            float2 v0, v1;
            v0.x = fmaf((float)acc[mt][nt][0], sa0 * sb0, bv.x);
            v0.y = fmaf((float)acc[mt][nt][1], sa0 * sb1, bv.y);
            v1.x = fmaf((float)acc[mt][nt][2], sa1 * sb0, bv.x);
            v1.y = fmaf((float)acc[mt][nt][3], sa1 * sb1, bv.y);
            *(float2*)(out + (size_t)row * O_DIM + col)       = v0;
            *(float2*)(out + (size_t)(row + 8) * O_DIM + col) = v1;
        }
    }
}

// ---------------- launch ------------------------------------------------------
extern "C" void kernel_launch(void* const* d_in, const int* in_sizes, int n_in,
                              void* d_out, int out_size) {
    const float* x     = (const float*)d_in[0];
    const float* e1w   = (const float*)d_in[1];
    const float* e2w   = (const float*)d_in[2];
    const float* wvals = (const float*)d_in[3];
    const float* bvals = (const float*)d_in[4];
    const int*   e1p   = (const int*)d_in[5];
    const int*   e2p   = (const int*)d_in[6];
    const int*   wrows = (const int*)d_in[7];
    const int*   wcols = (const int*)d_in[8];
    const int*   bidx  = (const int*)d_in[9];
    float* out = (float*)d_out;

    cudaFuncSetAttribute(gemm_kernel, cudaFuncAttributeMaxDynamicSharedMemorySize,
                         DYN_SMEM);

    zero_kernel<<<(O_DIM * F2_DIM + 255) / 256, 256>>>();
    scatter_kernel<<<(NNZ_DIM + 255) / 256, 256>>>(wvals, wrows, wcols, bvals, bidx);
    convw_kernel<<<O_DIM, 256>>>();
    build_a_kernel<<<B_DIM, 256>>>(x, e1w, e2w, e1p, e2p);

    dim3 grid(B_DIM / BM, O_DIM / BN);
    gemm_kernel<<<grid, 256, DYN_SMEM>>>(out);
}

// round 6
// speedup vs baseline: 6.8525x; 6.8525x over previous
#include <cuda_runtime.h>
#include <cuda_fp16.h>
#include <stdint.h>

#define B_DIM   8192
#define F0_DIM  2048
#define F1_DIM  2304
#define F2_DIM  2560
#define O_DIM   1024
#define NNZ_DIM 262144
#define NB_DIM  1024

// ---------------- scratch (device globals; no allocation allowed) -------------
__device__ float g_W[O_DIM * F2_DIM];
__device__ float g_bias[O_DIM];
__device__ __half g_A[(size_t)B_DIM * F2_DIM];    // 42 MB, fp16 h
__device__ __half g_Wc[(size_t)O_DIM * F2_DIM];   // 5.2 MB, fp16 W

// ---------------- helpers -----------------------------------------------------
__device__ __forceinline__ uint32_t smem_u32(const void* p) {
    uint32_t a;
    asm("{ .reg .u64 t; cvta.to.shared.u64 t, %1; cvt.u32.u64 %0, t; }"
        : "=r"(a) : "l"(p));
    return a;
}

#define SW128(off) ((uint32_t)(off) ^ ((((uint32_t)(off)) >> 3) & 0x70u))

__device__ __forceinline__ void cp_async16(uint32_t saddr, const void* gptr) {
    asm volatile("cp.async.cg.shared.global [%0], [%1], 16;\n"
                 :: "r"(saddr), "l"(gptr));
}

__device__ __forceinline__ void ldsm_x4(uint32_t* r, uint32_t addr) {
    asm volatile("ldmatrix.sync.aligned.m8n8.x4.shared.b16 {%0,%1,%2,%3}, [%4];"
                 : "=r"(r[0]), "=r"(r[1]), "=r"(r[2]), "=r"(r[3]) : "r"(addr));
}

__device__ __forceinline__ void mma_f16(float* d, const uint32_t* a, const uint32_t* b) {
    asm volatile(
        "mma.sync.aligned.m16n8k16.row.col.f32.f16.f16.f32 "
        "{%0,%1,%2,%3}, {%4,%5,%6,%7}, {%8,%9}, {%0,%1,%2,%3};\n"
        : "+f"(d[0]), "+f"(d[1]), "+f"(d[2]), "+f"(d[3])
        : "r"(a[0]), "r"(a[1]), "r"(a[2]), "r"(a[3]), "r"(b[0]), "r"(b[1]));
}

// ---------------- prologue kernels -------------------------------------------
__global__ void zero_kernel() {
    int i = blockIdx.x * blockDim.x + threadIdx.x;
    if (i < O_DIM * F2_DIM) g_W[i] = 0.0f;
    if (i < O_DIM) g_bias[i] = 0.0f;
}

__global__ void scatter_kernel(const float* __restrict__ w_vals,
                               const int*   __restrict__ w_rows,
                               const int*   __restrict__ w_cols,
                               const float* __restrict__ b_vals,
                               const int*   __restrict__ b_idx) {
    int i = blockIdx.x * blockDim.x + threadIdx.x;
    if (i < NNZ_DIM)
        atomicAdd(&g_W[w_rows[i] * F2_DIM + w_cols[i]], w_vals[i]);
    if (i < NB_DIM)
        atomicAdd(&g_bias[b_idx[i]], b_vals[i]);
}

__global__ void convw_kernel() {
    int i = blockIdx.x * blockDim.x + threadIdx.x;
    if (i >= O_DIM * F2_DIM / 4) return;
    float4 v = *(const float4*)(g_W + i * 4);
    __half2 p0 = __floats2half2_rn(v.x, v.y);
    __half2 p1 = __floats2half2_rn(v.z, v.w);
    *(__half2*)(g_Wc + i * 4)     = p0;
    *(__half2*)(g_Wc + i * 4 + 2) = p1;
}

// one block per batch row; all gathers hit smem, GMEM fully coalesced
__global__ void __launch_bounds__(256)
build_a_kernel(const float* __restrict__ x,
               const float* __restrict__ e1w,
               const float* __restrict__ e2w,
               const int*   __restrict__ e1p,
               const int*   __restrict__ e2p) {
    __shared__ float sh[F2_DIM];
    const int tid = threadIdx.x;
    const int b = blockIdx.x;

    const float4* xr = (const float4*)(x + (size_t)b * F0_DIM);
#pragma unroll
    for (int t = 0; t < F0_DIM / 4 / 256; t++)          // 2 iters
        ((float4*)sh)[tid + t * 256] = xr[tid + t * 256];
    __syncthreads();

    {   // E1 == 256 == blockDim
        int c = tid;
        float t = sh[__ldg(&e1p[c])] * __ldg(&e1w[c]);
        sh[F0_DIM + c] = fmaxf(t, 0.0f);
    }
    __syncthreads();
    {   // E2 == 256
        int c = tid;
        float t = sh[__ldg(&e2p[c])] * __ldg(&e2w[c]);
        sh[F1_DIM + c] = fmaxf(t, 0.0f);
    }
    __syncthreads();

    __half* base = g_A + (size_t)b * F2_DIM;
#pragma unroll
    for (int t = 0; t < F2_DIM / 4 / 256 + 1; t++) {    // 2560/1024 -> 3 iters
        int i = tid + t * 256;
        if (i < F2_DIM / 4) {
            float4 v = *(const float4*)(sh + i * 4);
            __half2 p0 = __floats2half2_rn(v.x, v.y);
            __half2 p1 = __floats2half2_rn(v.z, v.w);
            *(__half2*)(base + i * 4)     = p0;
            *(__half2*)(base + i * 4 + 2) = p1;
        }
    }
}

// ---------------- fp16 HMMA GEMM: out = A @ Wc^T + bias -----------------------
#define BM 128
#define BN 256
#define BK 64
#define STAGES 4
#define A_STAGE (BM * BK * 2)               /* 16384 B */
#define B_STAGE (BN * BK * 2)               /* 32768 B */
#define STAGE_BYTES (A_STAGE + B_STAGE)     /* 49152 B */
#define KT (F2_DIM / BK)                    /* 40 */
#define DYN_SMEM (STAGES * STAGE_BYTES)     /* 196608 B */

__global__ void __launch_bounds__(256, 1)
gemm_kernel(float* __restrict__ out) {
    extern __shared__ char dynsm[];
    const int tid  = threadIdx.x;
    const int wid  = tid >> 5;
    const int lane = tid & 31;
    const int wm   = wid >> 2;       // 0..1, 64 rows each
    const int wn   = wid & 3;        // 0..3, 64 cols each
    const int m0 = blockIdx.x * BM;
    const int n0 = blockIdx.y * BN;
    const uint32_t smbase = smem_u32(dynsm);

    float acc[4][8][4];
#pragma unroll
    for (int mt = 0; mt < 4; mt++)
#pragma unroll
        for (int nt = 0; nt < 8; nt++)
#pragma unroll
            for (int r = 0; r < 4; r++) acc[mt][nt][r] = 0.0f;

    // ldmatrix lane address components (logical, pre-swizzle, byte units)
    const uint32_t a_row = (uint32_t)(wm * 64 + (lane & 15));
    const uint32_t a_col = (uint32_t)((lane >> 4) * 16);
    const uint32_t b_row = (uint32_t)(wn * 64 + (lane & 7) + ((lane >> 4) << 3));
    const uint32_t b_col = (uint32_t)(((lane >> 3) & 1) * 16);

    auto load_tile = [&](int s, int kt) {
        int k0 = kt * BK;
        uint32_t As = smbase + s * STAGE_BYTES;
        uint32_t Bs = As + A_STAGE;
        const char* gA = (const char*)g_A  + (size_t)k0 * 2;
        const char* gB = (const char*)g_Wc + (size_t)k0 * 2;
#pragma unroll
        for (int t = 0; t < 4; t++) {                    // A: 1024 16B ops
            int o = tid + t * 256;
            int r = o >> 3;
            int c = (o & 7) * 16;
            cp_async16(As + SW128(r * 128 + c),
                       gA + (size_t)(m0 + r) * (F2_DIM * 2) + c);
        }
#pragma unroll
        for (int t = 0; t < 8; t++) {                    // B: 2048 16B ops
            int o = tid + t * 256;
            int r = o >> 3;
            int c = (o & 7) * 16;
            cp_async16(Bs + SW128(r * 128 + c),
                       gB + (size_t)(n0 + r) * (F2_DIM * 2) + c);
        }
    };

#pragma unroll
    for (int s = 0; s < STAGES - 1; s++) {
        load_tile(s, s);
        asm volatile("cp.async.commit_group;\n");
    }

    for (int kt = 0; kt < KT; kt++) {
        asm volatile("cp.async.wait_group %0;\n" :: "n"(STAGES - 2));
        __syncthreads();

        int kn = kt + STAGES - 1;
        if (kn < KT) load_tile(kn & (STAGES - 1), kn);
        asm volatile("cp.async.commit_group;\n");

        const uint32_t As = smbase + (kt & (STAGES - 1)) * STAGE_BYTES;
        const uint32_t Bs = As + A_STAGE;
#pragma unroll
        for (int ks = 0; ks < 4; ks++) {                 // BK=64 -> 4 k16 steps
            uint32_t a[4][4], b[4][4];
#pragma unroll
            for (int mt = 0; mt < 4; mt++)
                ldsm_x4(a[mt], As + SW128((a_row + mt * 16) * 128 + ks * 32 + a_col));
#pragma unroll
            for (int n2 = 0; n2 < 4; n2++)
                ldsm_x4(b[n2], Bs + SW128((b_row + n2 * 16) * 128 + ks * 32 + b_col));
#pragma unroll
            for (int mt = 0; mt < 4; mt++)
#pragma unroll
                for (int nt = 0; nt < 8; nt++)
                    mma_f16(acc[mt][nt], a[mt], &b[nt >> 1][(nt & 1) * 2]);
        }
    }

    // epilogue: + bias, float2 stores
    const int r0 = m0 + wm * 64 + (lane >> 2);
    const int c0 = n0 + wn * 64 + (lane & 3) * 2;
#pragma unroll
    for (int mt = 0; mt < 4; mt++) {
        int row = r0 + mt * 16;
#pragma unroll
        for (int nt = 0; nt < 8; nt++) {
            int col = c0 + nt * 8;
            float2 bv = *(const float2*)(g_bias + col);
            float2 v0 = make_float2(acc[mt][nt][0] + bv.x, acc[mt][nt][1] + bv.y);
            float2 v1 = make_float2(acc[mt][nt][2] + bv.x, acc[mt][nt][3] + bv.y);
            *(float2*)(out + (size_t)row * O_DIM + col)       = v0;
            *(float2*)(out + (size_t)(row + 8) * O_DIM + col) = v1;
        }
    }
}

// ---------------- launch ------------------------------------------------------
extern "C" void kernel_launch(void* const* d_in, const int* in_sizes, int n_in,
                              void* d_out, int out_size) {
    const float* x     = (const float*)d_in[0];
    const float* e1w   = (const float*)d_in[1];
    const float* e2w   = (const float*)d_in[2];
    const float* wvals = (const float*)d_in[3];
    const float* bvals = (const float*)d_in[4];
    const int*   e1p   = (const int*)d_in[5];
    const int*   e2p   = (const int*)d_in[6];
    const int*   wrows = (const int*)d_in[7];
    const int*   wcols = (const int*)d_in[8];
    const int*   bidx  = (const int*)d_in[9];
    float* out = (float*)d_out;

    cudaFuncSetAttribute(gemm_kernel, cudaFuncAttributeMaxDynamicSharedMemorySize,
                         DYN_SMEM);

    zero_kernel<<<(O_DIM * F2_DIM + 255) / 256, 256>>>();
    scatter_kernel<<<(NNZ_DIM + 255) / 256, 256>>>(wvals, wrows, wcols, bvals, bidx);
    convw_kernel<<<(O_DIM * F2_DIM / 4 + 255) / 256, 256>>>();
    build_a_kernel<<<B_DIM, 256>>>(x, e1w, e2w, e1p, e2p);

    dim3 grid(B_DIM / BM, O_DIM / BN);
    gemm_kernel<<<grid, 256, DYN_SMEM>>>(out);
}